// round 1
// baseline (speedup 1.0000x reference)
#include <cuda_runtime.h>
#include <math.h>

#define N_NODES 2000000
#define N_DAGS  20000
#define N_OBS   1000

// ---------------- device scratch (no allocations allowed) ----------------
__device__ int      g_dag_off[N_DAGS + 1];
__device__ int      g_obs_off[N_OBS + 1];
__device__ float    g_dagc[N_DAGS * 32];   // dag_summaries @ W1[37:69] + b1
__device__ float    g_globc[N_OBS * 32];   // global_summaries @ W1[69:101]
__device__ unsigned g_max_bits;
__device__ double   g_sum;
__device__ float    g_inv;
__device__ int      g_mask_mode;           // 0 = uint8, 1 = int32, 2 = float32

// ordered-uint encoding of float (monotone for all finite floats)
__device__ __forceinline__ unsigned enc_f(float f) {
    unsigned u = __float_as_uint(f);
    return (u & 0x80000000u) ? ~u : (u | 0x80000000u);
}
__device__ __forceinline__ float dec_f(unsigned u) {
    u = (u & 0x80000000u) ? (u & 0x7FFFFFFFu) : ~u;
    return __uint_as_float(u);
}

// ---------------- init ----------------
__global__ void init_kernel() {
    g_max_bits = 0u;      // encodes < any finite float
    g_sum = 0.0;
}

// ---------------- mask dtype detection ----------------
// bool/uint8: random 0/1 bytes everywhere.
// int32 0/1:  nonzero only at byte offset %4==0.
// float32 0.0/1.0: nonzero at %4==2 (0x80) and %4==3 (0x3F), zero at %4==0,1.
__global__ void detect_mask_kernel(const unsigned char* __restrict__ m) {
    __shared__ int c1, c2;
    if (threadIdx.x == 0) { c1 = 0; c2 = 0; }
    __syncthreads();
    int l1 = 0, l2 = 0;
    for (int i = threadIdx.x; i < 4096; i += blockDim.x) {
        unsigned char b = m[i];
        if (b) {
            int r = i & 3;
            if (r == 1) l1++;
            if (r == 2) l2++;
        }
    }
    atomicAdd(&c1, l1);
    atomicAdd(&c2, l2);
    __syncthreads();
    if (threadIdx.x == 0) {
        if (c1 == 0 && c2 == 0)      g_mask_mode = 1;  // int32
        else if (c1 == 0 && c2 > 0)  g_mask_mode = 2;  // float32
        else                         g_mask_mode = 0;  // uint8/bool
    }
}

// ---------------- exclusive prefix scan of ragged counts ----------------
// Auto-detects int32 vs int64: the int32-view of the buffer sums to exactly
// `total` iff dtype is int32 (JAX demotes int64 -> int32 with x64 disabled).
__global__ void scan_kernel(const void* __restrict__ counts_raw, int n, int total, int which) {
    __shared__ long long sbuf[1024];
    __shared__ long long carry;
    __shared__ int mode;
    int tid = threadIdx.x;
    int* off = (which == 0) ? g_dag_off : g_obs_off;

    const int* c32 = (const int*)counts_raw;
    long long s = 0;
    for (int i = tid; i < n; i += 1024) s += (long long)c32[i];
    sbuf[tid] = s;
    __syncthreads();
    for (int st = 512; st; st >>= 1) {
        if (tid < st) sbuf[tid] += sbuf[tid + st];
        __syncthreads();
    }
    if (tid == 0) {
        mode = (sbuf[0] == (long long)total) ? 0 : 1;
        carry = 0;
    }
    __syncthreads();

    const long long* c64 = (const long long*)counts_raw;
    for (int base = 0; base < n; base += 1024) {
        int i = base + tid;
        long long v = 0;
        if (i < n) v = (mode == 0) ? (long long)c32[i] : c64[i];
        sbuf[tid] = v;
        __syncthreads();
        #pragma unroll
        for (int st = 1; st < 1024; st <<= 1) {
            long long t = (tid >= st) ? sbuf[tid - st] : 0;
            __syncthreads();
            sbuf[tid] += t;
            __syncthreads();
        }
        long long incl = sbuf[tid];
        if (i < n) off[i] = (int)(carry + incl - v);   // exclusive prefix
        __syncthreads();
        if (tid == 0) carry += sbuf[1023];
        __syncthreads();
    }
    if (tid == 0) off[n] = (int)carry;
}

// ---------------- precomputed layer-1 contributions ----------------
__global__ void dag_contrib_kernel(const float* __restrict__ dag_sum,
                                   const float* __restrict__ W1,
                                   const float* __restrict__ b1) {
    int idx = blockIdx.x * blockDim.x + threadIdx.x;
    if (idx >= N_DAGS * 32) return;
    int d = idx >> 5, j = idx & 31;
    const float* row = dag_sum + d * 32;
    float acc = b1[j];
    #pragma unroll
    for (int k = 0; k < 32; k++)
        acc = fmaf(row[k], W1[(37 + k) * 32 + j], acc);
    g_dagc[idx] = acc;
}

__global__ void glob_contrib_kernel(const float* __restrict__ glob_sum,
                                    const float* __restrict__ W1) {
    int idx = blockIdx.x * blockDim.x + threadIdx.x;
    if (idx >= N_OBS * 32) return;
    int o = idx >> 5, j = idx & 31;
    const float* row = glob_sum + o * 32;
    float acc = 0.f;
    #pragma unroll
    for (int k = 0; k < 32; k++)
        acc = fmaf(row[k], W1[(69 + k) * 32 + j], acc);
    g_globc[idx] = acc;
}

// ---------------- main MLP + masked scores + global max ----------------
__global__ __launch_bounds__(256)
void main_kernel(const float* __restrict__ x,
                 const float* __restrict__ emb,
                 const void* __restrict__ mask_raw,
                 const float* __restrict__ W1,
                 const float* __restrict__ W2, const float* __restrict__ b2,
                 const float* __restrict__ W3, const float* __restrict__ b3,
                 const float* __restrict__ W4, const float* __restrict__ b4,
                 float* __restrict__ out) {
    __shared__ float sW1[37 * 32];
    __shared__ float sW2[32 * 16];
    __shared__ float sW3[16 * 8];
    __shared__ float sW4[8];
    __shared__ float sb2[16], sb3[8], sb4;

    int tid = threadIdx.x;
    for (int t = tid; t < 37 * 32; t += blockDim.x) sW1[t] = W1[t];
    for (int t = tid; t < 32 * 16; t += blockDim.x) sW2[t] = W2[t];
    for (int t = tid; t < 16 * 8;  t += blockDim.x) sW3[t] = W3[t];
    if (tid < 8)  sW4[tid] = W4[tid];
    if (tid < 16) sb2[tid] = b2[tid];
    if (tid < 8)  sb3[tid] = b3[tid];
    if (tid == 0) sb4 = b4[0];
    __syncthreads();

    int i = blockIdx.x * blockDim.x + tid;
    float score = -3.402823466e+38f;
    if (i < N_NODES) {
        // segment ids via binary search on exclusive prefix offsets
        int lo = 0, hi = N_DAGS - 1;
        while (lo < hi) {
            int mid = (lo + hi + 1) >> 1;
            if (g_dag_off[mid] <= i) lo = mid; else hi = mid - 1;
        }
        int dg = lo;
        lo = 0; hi = N_OBS - 1;
        while (lo < hi) {
            int mid = (lo + hi + 1) >> 1;
            if (g_obs_off[mid] <= i) lo = mid; else hi = mid - 1;
        }
        int ob = lo;

        float acc[32];
        const float* dc = g_dagc + dg * 32;
        const float* gc = g_globc + ob * 32;
        #pragma unroll
        for (int j = 0; j < 32; j++) acc[j] = dc[j] + gc[j];

        // x part (5 features)
        const float* xr = x + (long long)i * 5;
        #pragma unroll
        for (int k = 0; k < 5; k++) {
            float v = xr[k];
            const float* w = sW1 + k * 32;
            #pragma unroll
            for (int j = 0; j < 32; j++) acc[j] = fmaf(v, w[j], acc[j]);
        }
        // embedding part (32 features), vectorized loads
        const float4* er = (const float4*)(emb + (long long)i * 32);
        #pragma unroll
        for (int k4 = 0; k4 < 8; k4++) {
            float4 e = er[k4];
            const float* w = sW1 + (5 + k4 * 4) * 32;
            #pragma unroll
            for (int j = 0; j < 32; j++) {
                float a = acc[j];
                a = fmaf(e.x, w[j],      a);
                a = fmaf(e.y, w[32 + j], a);
                a = fmaf(e.z, w[64 + j], a);
                a = fmaf(e.w, w[96 + j], a);
                acc[j] = a;
            }
        }

        // layer 2: relu(acc) @ W2 + b2
        float h2[16];
        #pragma unroll
        for (int j = 0; j < 16; j++) h2[j] = sb2[j];
        #pragma unroll
        for (int k = 0; k < 32; k++) {
            float v = fmaxf(acc[k], 0.f);
            const float* w = sW2 + k * 16;
            #pragma unroll
            for (int j = 0; j < 16; j++) h2[j] = fmaf(v, w[j], h2[j]);
        }
        // layer 3
        float h3[8];
        #pragma unroll
        for (int j = 0; j < 8; j++) h3[j] = sb3[j];
        #pragma unroll
        for (int k = 0; k < 16; k++) {
            float v = fmaxf(h2[k], 0.f);
            const float* w = sW3 + k * 8;
            #pragma unroll
            for (int j = 0; j < 8; j++) h3[j] = fmaf(v, w[j], h3[j]);
        }
        // layer 4 -> scalar score
        float s = sb4;
        #pragma unroll
        for (int k = 0; k < 8; k++) s = fmaf(fmaxf(h3[k], 0.f), sW4[k], s);

        // mask (dtype-adaptive)
        bool mv;
        int mode = g_mask_mode;
        if (mode == 0)      mv = ((const unsigned char*)mask_raw)[i] != 0;
        else if (mode == 1) mv = ((const int*)mask_raw)[i] != 0;
        else                mv = ((const float*)mask_raw)[i] != 0.f;
        if (mv) score = s;
        out[i] = score;
    }

    // block max -> global atomic max
    float m = score;
    #pragma unroll
    for (int o = 16; o; o >>= 1) m = fmaxf(m, __shfl_xor_sync(0xffffffffu, m, o));
    __shared__ float wmax[8];
    if ((tid & 31) == 0) wmax[tid >> 5] = m;
    __syncthreads();
    if (tid == 0) {
        float bm = wmax[0];
        #pragma unroll
        for (int w = 1; w < 8; w++) bm = fmaxf(bm, wmax[w]);
        atomicMax(&g_max_bits, enc_f(bm));
    }
}

// ---------------- softmax: exp + sum ----------------
__global__ void sum_kernel(float* __restrict__ out, int n) {
    float mx = dec_f(g_max_bits);
    double part = 0.0;
    for (int i = blockIdx.x * blockDim.x + threadIdx.x; i < n; i += gridDim.x * blockDim.x) {
        float e = expf(out[i] - mx);
        out[i] = e;
        part += (double)e;
    }
    __shared__ double sd[256];
    sd[threadIdx.x] = part;
    __syncthreads();
    for (int st = 128; st; st >>= 1) {
        if (threadIdx.x < st) sd[threadIdx.x] += sd[threadIdx.x + st];
        __syncthreads();
    }
    if (threadIdx.x == 0) atomicAdd(&g_sum, sd[0]);
}

__global__ void inv_kernel() {
    g_inv = (float)(1.0 / g_sum);
}

__global__ void fin_kernel(float* __restrict__ out, int n) {
    float inv = g_inv;
    for (int i = blockIdx.x * blockDim.x + threadIdx.x; i < n; i += gridDim.x * blockDim.x)
        out[i] *= inv;
}

// ---------------- launch ----------------
extern "C" void kernel_launch(void* const* d_in, const int* in_sizes, int n_in,
                              void* d_out, int out_size) {
    const float* x        = (const float*)d_in[0];
    const float* emb      = (const float*)d_in[1];
    const float* dag_sum  = (const float*)d_in[2];
    const float* glob_sum = (const float*)d_in[3];
    const void*  cnt_dag  = d_in[4];
    const void*  cnt_obs  = d_in[5];
    const void*  mask     = d_in[6];
    const float* W1 = (const float*)d_in[7];
    const float* b1 = (const float*)d_in[8];
    const float* W2 = (const float*)d_in[9];
    const float* b2 = (const float*)d_in[10];
    const float* W3 = (const float*)d_in[11];
    const float* b3 = (const float*)d_in[12];
    const float* W4 = (const float*)d_in[13];
    const float* b4 = (const float*)d_in[14];
    float* out = (float*)d_out;

    init_kernel<<<1, 1>>>();
    detect_mask_kernel<<<1, 256>>>((const unsigned char*)mask);
    scan_kernel<<<1, 1024>>>(cnt_dag, N_DAGS, N_NODES, 0);
    scan_kernel<<<1, 1024>>>(cnt_obs, N_OBS, N_NODES, 1);
    dag_contrib_kernel<<<(N_DAGS * 32 + 255) / 256, 256>>>(dag_sum, W1, b1);
    glob_contrib_kernel<<<(N_OBS * 32 + 255) / 256, 256>>>(glob_sum, W1);
    main_kernel<<<(N_NODES + 255) / 256, 256>>>(x, emb, mask, W1, W2, b2, W3, b3, W4, b4, out);
    sum_kernel<<<1024, 256>>>(out, N_NODES);
    inv_kernel<<<1, 1>>>();
    fin_kernel<<<2048, 256>>>(out, N_NODES);
}

// round 2
// speedup vs baseline: 1.0115x; 1.0115x over previous
#include <cuda_runtime.h>
#include <math.h>

#define N_NODES 2000000
#define N_DAGS  20000
#define N_OBS   1000

// ---------------- device scratch (no allocations allowed) ----------------
__device__ int      g_dag_off[N_DAGS + 1];
__device__ int      g_obs_off[N_OBS + 1];
__device__ __align__(16) float g_dagc[N_DAGS * 32];   // dag_summaries @ W1[37:69] + b1
__device__ __align__(16) float g_globc[N_OBS * 32];   // global_summaries @ W1[69:101]
__device__ unsigned g_max_bits;
__device__ double   g_sum;
__device__ float    g_inv;
__device__ int      g_mask_mode;           // 0 = uint8, 1 = int32, 2 = float32

typedef unsigned long long ull;

// ---------------- f32x2 packed math helpers (Blackwell) ----------------
__device__ __forceinline__ ull dup2(float v) {
    ull r; asm("mov.b64 %0, {%1, %1};" : "=l"(r) : "f"(v)); return r;
}
__device__ __forceinline__ ull pk2(float lo, float hi) {
    ull r; asm("mov.b64 %0, {%1, %2};" : "=l"(r) : "f"(lo), "f"(hi)); return r;
}
__device__ __forceinline__ float2 up2(ull v) {
    float2 f; asm("mov.b64 {%0, %1}, %2;" : "=f"(f.x), "=f"(f.y) : "l"(v)); return f;
}
__device__ __forceinline__ void fma2(ull& d, ull a, ull b) {
    asm("fma.rn.f32x2 %0, %1, %2, %0;" : "+l"(d) : "l"(a), "l"(b));
}
__device__ __forceinline__ ull add2(ull a, ull b) {
    ull r; asm("add.rn.f32x2 %0, %1, %2;" : "=l"(r) : "l"(a), "l"(b)); return r;
}

// ordered-uint encoding of float (monotone for all finite floats)
__device__ __forceinline__ unsigned enc_f(float f) {
    unsigned u = __float_as_uint(f);
    return (u & 0x80000000u) ? ~u : (u | 0x80000000u);
}
__device__ __forceinline__ float dec_f(unsigned u) {
    u = (u & 0x80000000u) ? (u & 0x7FFFFFFFu) : ~u;
    return __uint_as_float(u);
}

// ---------------- init ----------------
__global__ void init_kernel() {
    g_max_bits = 0u;      // encodes < any finite float
    g_sum = 0.0;
}

// ---------------- mask dtype detection ----------------
__global__ void detect_mask_kernel(const unsigned char* __restrict__ m) {
    __shared__ int c1, c2;
    if (threadIdx.x == 0) { c1 = 0; c2 = 0; }
    __syncthreads();
    int l1 = 0, l2 = 0;
    for (int i = threadIdx.x; i < 4096; i += blockDim.x) {
        unsigned char b = m[i];
        if (b) {
            int r = i & 3;
            if (r == 1) l1++;
            if (r == 2) l2++;
        }
    }
    atomicAdd(&c1, l1);
    atomicAdd(&c2, l2);
    __syncthreads();
    if (threadIdx.x == 0) {
        if (c1 == 0 && c2 == 0)      g_mask_mode = 1;  // int32
        else if (c1 == 0 && c2 > 0)  g_mask_mode = 2;  // float32
        else                         g_mask_mode = 0;  // uint8/bool
    }
}

// ---------------- exclusive prefix scan of ragged counts ----------------
__global__ void scan_kernel(const void* __restrict__ counts_raw, int n, int total, int which) {
    __shared__ long long sbuf[1024];
    __shared__ long long carry;
    __shared__ int mode;
    int tid = threadIdx.x;
    int* off = (which == 0) ? g_dag_off : g_obs_off;

    const int* c32 = (const int*)counts_raw;
    long long s = 0;
    for (int i = tid; i < n; i += 1024) s += (long long)c32[i];
    sbuf[tid] = s;
    __syncthreads();
    for (int st = 512; st; st >>= 1) {
        if (tid < st) sbuf[tid] += sbuf[tid + st];
        __syncthreads();
    }
    if (tid == 0) {
        mode = (sbuf[0] == (long long)total) ? 0 : 1;
        carry = 0;
    }
    __syncthreads();

    const long long* c64 = (const long long*)counts_raw;
    for (int base = 0; base < n; base += 1024) {
        int i = base + tid;
        long long v = 0;
        if (i < n) v = (mode == 0) ? (long long)c32[i] : c64[i];
        sbuf[tid] = v;
        __syncthreads();
        #pragma unroll
        for (int st = 1; st < 1024; st <<= 1) {
            long long t = (tid >= st) ? sbuf[tid - st] : 0;
            __syncthreads();
            sbuf[tid] += t;
            __syncthreads();
        }
        long long incl = sbuf[tid];
        if (i < n) off[i] = (int)(carry + incl - v);   // exclusive prefix
        __syncthreads();
        if (tid == 0) carry += sbuf[1023];
        __syncthreads();
    }
    if (tid == 0) off[n] = (int)carry;
}

// ---------------- precomputed layer-1 contributions ----------------
__global__ void dag_contrib_kernel(const float* __restrict__ dag_sum,
                                   const float* __restrict__ W1,
                                   const float* __restrict__ b1) {
    int idx = blockIdx.x * blockDim.x + threadIdx.x;
    if (idx >= N_DAGS * 32) return;
    int d = idx >> 5, j = idx & 31;
    const float* row = dag_sum + d * 32;
    float acc = b1[j];
    #pragma unroll
    for (int k = 0; k < 32; k++)
        acc = fmaf(row[k], W1[(37 + k) * 32 + j], acc);
    g_dagc[idx] = acc;
}

__global__ void glob_contrib_kernel(const float* __restrict__ glob_sum,
                                    const float* __restrict__ W1) {
    int idx = blockIdx.x * blockDim.x + threadIdx.x;
    if (idx >= N_OBS * 32) return;
    int o = idx >> 5, j = idx & 31;
    const float* row = glob_sum + o * 32;
    float acc = 0.f;
    #pragma unroll
    for (int k = 0; k < 32; k++)
        acc = fmaf(row[k], W1[(69 + k) * 32 + j], acc);
    g_globc[idx] = acc;
}

// ---------------- main MLP + masked scores + global max ----------------
__global__ __launch_bounds__(256)
void main_kernel(const float* __restrict__ x,
                 const float* __restrict__ emb,
                 const void* __restrict__ mask_raw,
                 const float* __restrict__ W1,
                 const float* __restrict__ W2, const float* __restrict__ b2,
                 const float* __restrict__ W3, const float* __restrict__ b3,
                 const float* __restrict__ W4, const float* __restrict__ b4,
                 float* __restrict__ out) {
    __shared__ __align__(16) float sW1[37 * 32];
    __shared__ __align__(16) float sW2[32 * 16];
    __shared__ __align__(16) float sW3[16 * 8];
    __shared__ __align__(16) float sW4[8];
    __shared__ __align__(16) float sb2[16];
    __shared__ __align__(16) float sb3[8];
    __shared__ float sb4;

    int tid = threadIdx.x;
    for (int t = tid; t < 37 * 32; t += blockDim.x) sW1[t] = W1[t];
    for (int t = tid; t < 32 * 16; t += blockDim.x) sW2[t] = W2[t];
    for (int t = tid; t < 16 * 8;  t += blockDim.x) sW3[t] = W3[t];
    if (tid < 8)  sW4[tid] = W4[tid];
    if (tid < 16) sb2[tid] = b2[tid];
    if (tid < 8)  sb3[tid] = b3[tid];
    if (tid == 0) sb4 = b4[0];
    __syncthreads();

    int i = blockIdx.x * blockDim.x + tid;
    float score = -3.402823466e+38f;
    if (i < N_NODES) {
        // segment ids via binary search on exclusive prefix offsets
        int lo = 0, hi = N_DAGS - 1;
        while (lo < hi) {
            int mid = (lo + hi + 1) >> 1;
            if (g_dag_off[mid] <= i) lo = mid; else hi = mid - 1;
        }
        int dg = lo;
        lo = 0; hi = N_OBS - 1;
        while (lo < hi) {
            int mid = (lo + hi + 1) >> 1;
            if (g_obs_off[mid] <= i) lo = mid; else hi = mid - 1;
        }
        int ob = lo;

        // ---- layer 1: acc[32] as 16 packed f32x2 ----
        ull acc[16];
        {
            const ull* dc = (const ull*)(g_dagc + dg * 32);
            const ull* gc = (const ull*)(g_globc + ob * 32);
            #pragma unroll
            for (int j = 0; j < 16; j++) acc[j] = add2(dc[j], gc[j]);
        }

        // x part (5 features)
        const float* xr = x + (long long)i * 5;
        #pragma unroll
        for (int k = 0; k < 5; k++) {
            ull v = dup2(xr[k]);
            const ull* w = (const ull*)(sW1 + k * 32);
            #pragma unroll
            for (int j = 0; j < 16; j++) fma2(acc[j], v, w[j]);
        }
        // embedding part (32 features), vectorized loads
        const float4* er = (const float4*)(emb + (long long)i * 32);
        #pragma unroll
        for (int k4 = 0; k4 < 8; k4++) {
            float4 e = er[k4];
            ull v0 = dup2(e.x), v1 = dup2(e.y), v2 = dup2(e.z), v3 = dup2(e.w);
            const ull* w0 = (const ull*)(sW1 + (5 + k4 * 4) * 32);
            const ull* w1 = w0 + 16;
            const ull* w2 = w0 + 32;
            const ull* w3 = w0 + 48;
            #pragma unroll
            for (int j = 0; j < 16; j++) {
                fma2(acc[j], v0, w0[j]);
                fma2(acc[j], v1, w1[j]);
                fma2(acc[j], v2, w2[j]);
                fma2(acc[j], v3, w3[j]);
            }
        }

        // ---- layer 2: relu(acc) @ W2 + b2, h2[16] as 8 packed ----
        ull h2[8];
        {
            const ull* bb = (const ull*)sb2;
            #pragma unroll
            for (int t = 0; t < 8; t++) h2[t] = bb[t];
        }
        #pragma unroll
        for (int j = 0; j < 16; j++) {
            float2 a = up2(acc[j]);
            ull d0 = dup2(fmaxf(a.x, 0.f));
            ull d1 = dup2(fmaxf(a.y, 0.f));
            const ull* w0 = (const ull*)(sW2 + (2 * j) * 16);
            const ull* w1 = w0 + 8;
            #pragma unroll
            for (int t = 0; t < 8; t++) {
                fma2(h2[t], d0, w0[t]);
                fma2(h2[t], d1, w1[t]);
            }
        }

        // ---- layer 3: h3[8] as 4 packed ----
        ull h3[4];
        {
            const ull* bb = (const ull*)sb3;
            #pragma unroll
            for (int t = 0; t < 4; t++) h3[t] = bb[t];
        }
        #pragma unroll
        for (int j = 0; j < 8; j++) {
            float2 a = up2(h2[j]);
            ull d0 = dup2(fmaxf(a.x, 0.f));
            ull d1 = dup2(fmaxf(a.y, 0.f));
            const ull* w0 = (const ull*)(sW3 + (2 * j) * 8);
            const ull* w1 = w0 + 4;
            #pragma unroll
            for (int t = 0; t < 4; t++) {
                fma2(h3[t], d0, w0[t]);
                fma2(h3[t], d1, w1[t]);
            }
        }

        // ---- layer 4 -> scalar score ----
        float s = sb4;
        #pragma unroll
        for (int j = 0; j < 4; j++) {
            float2 a = up2(h3[j]);
            s = fmaf(fmaxf(a.x, 0.f), sW4[2 * j],     s);
            s = fmaf(fmaxf(a.y, 0.f), sW4[2 * j + 1], s);
        }

        // mask (dtype-adaptive)
        bool mv;
        int mode = g_mask_mode;
        if (mode == 0)      mv = ((const unsigned char*)mask_raw)[i] != 0;
        else if (mode == 1) mv = ((const int*)mask_raw)[i] != 0;
        else                mv = ((const float*)mask_raw)[i] != 0.f;
        if (mv) score = s;
        out[i] = score;
    }

    // block max -> global atomic max
    float m = score;
    #pragma unroll
    for (int o = 16; o; o >>= 1) m = fmaxf(m, __shfl_xor_sync(0xffffffffu, m, o));
    __shared__ float wmax[8];
    if ((tid & 31) == 0) wmax[tid >> 5] = m;
    __syncthreads();
    if (tid == 0) {
        float bm = wmax[0];
        #pragma unroll
        for (int w = 1; w < 8; w++) bm = fmaxf(bm, wmax[w]);
        atomicMax(&g_max_bits, enc_f(bm));
    }
}

// ---------------- softmax: sum of exp (no write) ----------------
__global__ void sum_kernel(const float* __restrict__ out, int n) {
    float mx = dec_f(g_max_bits);
    double part = 0.0;
    for (int i = blockIdx.x * blockDim.x + threadIdx.x; i < n; i += gridDim.x * blockDim.x) {
        part += (double)expf(out[i] - mx);
    }
    __shared__ double sd[256];
    sd[threadIdx.x] = part;
    __syncthreads();
    for (int st = 128; st; st >>= 1) {
        if (threadIdx.x < st) sd[threadIdx.x] += sd[threadIdx.x + st];
        __syncthreads();
    }
    if (threadIdx.x == 0) atomicAdd(&g_sum, sd[0]);
}

__global__ void inv_kernel() {
    g_inv = (float)(1.0 / g_sum);
}

__global__ void fin_kernel(float* __restrict__ out, int n) {
    float inv = g_inv;
    float mx = dec_f(g_max_bits);
    for (int i = blockIdx.x * blockDim.x + threadIdx.x; i < n; i += gridDim.x * blockDim.x)
        out[i] = expf(out[i] - mx) * inv;
}

// ---------------- launch ----------------
extern "C" void kernel_launch(void* const* d_in, const int* in_sizes, int n_in,
                              void* d_out, int out_size) {
    const float* x        = (const float*)d_in[0];
    const float* emb      = (const float*)d_in[1];
    const float* dag_sum  = (const float*)d_in[2];
    const float* glob_sum = (const float*)d_in[3];
    const void*  cnt_dag  = d_in[4];
    const void*  cnt_obs  = d_in[5];
    const void*  mask     = d_in[6];
    const float* W1 = (const float*)d_in[7];
    const float* b1 = (const float*)d_in[8];
    const float* W2 = (const float*)d_in[9];
    const float* b2 = (const float*)d_in[10];
    const float* W3 = (const float*)d_in[11];
    const float* b3 = (const float*)d_in[12];
    const float* W4 = (const float*)d_in[13];
    const float* b4 = (const float*)d_in[14];
    float* out = (float*)d_out;

    init_kernel<<<1, 1>>>();
    detect_mask_kernel<<<1, 256>>>((const unsigned char*)mask);
    scan_kernel<<<1, 1024>>>(cnt_dag, N_DAGS, N_NODES, 0);
    scan_kernel<<<1, 1024>>>(cnt_obs, N_OBS, N_NODES, 1);
    dag_contrib_kernel<<<(N_DAGS * 32 + 255) / 256, 256>>>(dag_sum, W1, b1);
    glob_contrib_kernel<<<(N_OBS * 32 + 255) / 256, 256>>>(glob_sum, W1);
    main_kernel<<<(N_NODES + 255) / 256, 256>>>(x, emb, mask, W1, W2, b2, W3, b3, W4, b4, out);
    sum_kernel<<<1024, 256>>>(out, N_NODES);
    inv_kernel<<<1, 1>>>();
    fin_kernel<<<2048, 256>>>(out, N_NODES);
}